// round 17
// baseline (speedup 1.0000x reference)
#include <cuda_runtime.h>
#include <cuda_fp16.h>
#include <mma.h>
#include <math.h>
#include <stdint.h>

using namespace nvcuda;

#define TT   512
#define BB   256
#define IND  248
#define KP   256
#define HID  1024
#define CHUNK 512
#define SCAN_CTAS 128
#define HELPERS   20
#define NGRID     (SCAN_CTAS + HELPERS)
#define XRDY_TGT  32u   // tiles per timestep: 8 row-blocks x 4 col-groups

// ---------------------------------------------------------------------------
// Device globals
// ---------------------------------------------------------------------------
__device__ __half g_xp[(size_t)TT * BB * HID];    // xproj result (fp16)
__device__ __half g_xh[(size_t)TT * BB * KP];     // x (fp16, padded)
__device__ __half g_wih[HID * KP];                // W_ih (fp16)
__device__ __half g_whh[HID * HID];               // W_hh (fp16)
__device__ __half g_hf[2][BB * HID];              // hidden (fp16), ping-pong
__device__ float  g_zp[16][TT * BB];              // per-n-block z partials
__device__ float  g_zsum[BB * TT];                // reduced z, [b][t]
__device__ unsigned g_cnt[8 * 32];                // per-bb-group barrier, 128B apart
__device__ unsigned g_xready[TT];                 // per-timestep xproj tile counts

// ---------------------------------------------------------------------------
// helpers
// ---------------------------------------------------------------------------
__device__ __forceinline__ uint32_t smem_u32(const void* p) {
    uint32_t a;
    asm("{ .reg .u64 t; cvta.to.shared.u64 t, %1; cvt.u32.u64 %0, t; }" : "=r"(a) : "l"(p));
    return a;
}
__device__ __forceinline__ void cp16_ca(void* s, const void* g) {
    asm volatile("cp.async.ca.shared.global [%0], [%1], 16;" :: "r"(smem_u32(s)), "l"(g) : "memory");
}
__device__ __forceinline__ void cp16_cg(void* s, const void* g) {
    asm volatile("cp.async.cg.shared.global [%0], [%1], 16;" :: "r"(smem_u32(s)), "l"(g) : "memory");
}
#define CP_COMMIT() asm volatile("cp.async.commit_group;" ::: "memory")
#define CP_WAIT0()  asm volatile("cp.async.wait_group 0;" ::: "memory")
#define CP_WAIT1()  asm volatile("cp.async.wait_group 1;" ::: "memory")

__device__ __forceinline__ float fast_tanh(float x) {
    float r;
    asm("tanh.approx.f32 %0, %1;" : "=f"(r) : "f"(x));
    return r;
}

// ---------------------------------------------------------------------------
// init: zero h(-1), barrier counters, xready
// ---------------------------------------------------------------------------
__global__ void init_kernel() {
    int i = blockIdx.x * blockDim.x + threadIdx.x;
    if (i < BB * HID / 8) ((uint4*)g_hf[0])[i] = make_uint4(0, 0, 0, 0);
    if (i < 8 * 32) g_cnt[i] = 0;
    if (i < TT) g_xready[i] = 0;
}

// ---------------------------------------------------------------------------
// preps (vectorized, 8 elements/thread)
// ---------------------------------------------------------------------------
__global__ void prep_whh(const float* __restrict__ W_hh) {
    int i = blockIdx.x * blockDim.x + threadIdx.x;
    const float* src = W_hh + (size_t)i * 8;
    __half hb[8];
#pragma unroll
    for (int j = 0; j < 8; j++) hb[j] = __float2half(src[j]);
    *(uint4*)(g_whh + (size_t)i * 8) = *(uint4*)hb;
}
__global__ void prep_wih(const float* __restrict__ W_ih) {
    int i = blockIdx.x * blockDim.x + threadIdx.x;
    int row = i >> 5, g = i & 31;
    __half hb[8];
#pragma unroll
    for (int j = 0; j < 8; j++) {
        int col = g * 8 + j;
        hb[j] = __float2half((col < IND) ? W_ih[row * IND + col] : 0.0f);
    }
    *(uint4*)(g_wih + (size_t)row * KP + g * 8) = *(uint4*)hb;
}
__global__ void prep_x(const float* __restrict__ x) {
    size_t i = (size_t)blockIdx.x * blockDim.x + threadIdx.x;
    size_t row = i >> 5; int g = (int)(i & 31);
    __half hb[8];
    if (g < 31) {
        float4 v1 = __ldg((const float4*)(x + row * IND + g * 8));
        float4 v2 = __ldg((const float4*)(x + row * IND + g * 8 + 4));
        float v[8] = {v1.x, v1.y, v1.z, v1.w, v2.x, v2.y, v2.z, v2.w};
#pragma unroll
        for (int j = 0; j < 8; j++) hb[j] = __float2half(v[j]);
    } else {
#pragma unroll
        for (int j = 0; j < 8; j++) hb[j] = __float2half(0.0f);
    }
    *(uint4*)(g_xh + row * KP + g * 8) = *(uint4*)hb;
}

// ---------------------------------------------------------------------------
// Fused persistent kernel, grid = 148 CTAs:
//   CTAs [0,128): recurrence scan (R16 skeleton, verified local optimum)
//   CTAs [128,148): xproj helpers — hide xproj under the scan on idle SMs.
//
// Helper: 20 CTAs = 4 W-groups (256 cols each, W slice persistent in smem,
// 135KB) x 5 siblings (split the 8 row-blocks per timestep). Per 32x256 tile:
// 1024 cp.async for x (double-buffered across tiles), 64 MMAs/warp, epilogue
// bias+fp16 -> g_xp, then release-publish into g_xready[t].
// Scan: polls g_xready[t+1] inside the existing tid0 barrier spin (zero new
// syncs); pre-loop poll covers t=0.
//
// Scan smem (208128 B): sW[64][1032]h @0 | sA[2][32][520]h @132096
//   | sOut[32][72]f @198656 | sWout[64]f @207872
// Helper smem (203776 B, fits inside): hW[256][264]h @0 | hX[2][32][264]h
//   @135168 | hOut[32][264]f @168960 | hBias[256]f @202752
// ---------------------------------------------------------------------------
__global__ void __launch_bounds__(256, 1) step_fused(const float* __restrict__ W_out,
                                                     const float* __restrict__ b_ih,
                                                     const float* __restrict__ b_hh) {
    extern __shared__ char smem[];
    const int tid = threadIdx.x, wid = tid >> 5;

    if (blockIdx.x >= SCAN_CTAS) {
        // =================== HELPER ROLE: xproj producer ===================
        __half (*hW)[264]    = (__half(*)[264])(smem);
        __half (*hX)[32][264] = (__half(*)[32][264])(smem + 135168);
        float (*hOut)[264]   = (float(*)[264])(smem + 168960);
        float* hBias         = (float*)(smem + 202752);

        const int hid = blockIdx.x - SCAN_CTAS;       // 0..19
        const int grp = hid / 5;                      // W-group: cols [grp*256, +256)
        const int sib = hid % 5;                      // sibling within group
        const int wm = wid & 1, wn = wid >> 1;        // 2m x 4n warps (16 x 64 each)

        // Load persistent W_ih slice (256 n-rows x 256 k) once
        for (int i = tid; i < 8192; i += 256) {
            const int r = i >> 5, c8 = (i & 31) * 8;
            cp16_ca(&hW[r][c8], g_wih + (size_t)(grp * 256 + r) * KP + c8);
        }
        CP_COMMIT();
        hBias[tid] = b_ih[grp * 256 + tid] + b_hh[grp * 256 + tid];
        CP_WAIT0();
        __syncthreads();

        // tile list (t-major): sib<3 -> rb in {sib, sib+5}; else rb = sib
        const int ntiles = (sib < 3) ? 2 * TT : TT;

        auto issue_x = [&](int buf, int t, int rb) {
#pragma unroll
            for (int j = 0; j < 4; j++) {             // 1024 cp16
                const int idx = tid + j * 256;
                const int r = idx >> 5, c8 = (idx & 31) * 8;
                cp16_cg(&hX[buf][r][c8],
                        g_xh + (size_t)(t * BB + rb * 32 + r) * KP + c8);
            }
        };

        int t0 = 0, rb0 = sib;
        issue_x(0, t0, rb0); CP_COMMIT();

        for (int i = 0; i < ntiles; i++) {
            int t, rb;
            if (sib < 3) { t = i >> 1; rb = sib + 5 * (i & 1); }
            else         { t = i;      rb = sib; }

            CP_WAIT0();
            __syncthreads();
            if (i + 1 < ntiles) {
                int tn, rbn;
                if (sib < 3) { tn = (i + 1) >> 1; rbn = sib + 5 * ((i + 1) & 1); }
                else         { tn = i + 1;        rbn = sib; }
                issue_x((i + 1) & 1, tn, rbn); CP_COMMIT();
            }
            const int buf = i & 1;

            wmma::fragment<wmma::accumulator, 16, 16, 16, float> acc[4];
#pragma unroll
            for (int u = 0; u < 4; u++) wmma::fill_fragment(acc[u], 0.0f);
#pragma unroll
            for (int ks = 0; ks < KP; ks += 16) {
                wmma::fragment<wmma::matrix_a, 16, 16, 16, __half, wmma::row_major> ah;
                wmma::load_matrix_sync(ah, &hX[buf][wm * 16][ks], 264);
#pragma unroll
                for (int u = 0; u < 4; u++) {
                    wmma::fragment<wmma::matrix_b, 16, 16, 16, __half, wmma::col_major> bh;
                    wmma::load_matrix_sync(bh, &hW[wn * 64 + u * 16][ks], 264);
                    wmma::mma_sync(acc[u], ah, bh, acc[u]);
                }
            }
#pragma unroll
            for (int u = 0; u < 4; u++)
                wmma::store_matrix_sync(&hOut[wm * 16][wn * 64 + u * 16], acc[u], 264,
                                        wmma::mem_row_major);
            __syncthreads();

            // epilogue: bias + fp16, write 32x256 tile to g_xp
            const int r = tid >> 3, c0 = (tid & 7) * 32;
            __half* dst = g_xp + (size_t)(t * BB + rb * 32 + r) * HID + grp * 256 + c0;
#pragma unroll
            for (int v = 0; v < 4; v++) {
                __half hb[8];
#pragma unroll
                for (int j = 0; j < 8; j++) {
                    const int c = c0 + v * 8 + j;
                    hb[j] = __float2half(hOut[r][c] + hBias[c]);
                }
                *(uint4*)(dst + v * 8) = *(uint4*)hb;
            }
            __syncthreads();
            if (tid == 0) {
                __threadfence();                      // release tile stores
                atomicAdd(&g_xready[t], 1u);
            }
        }
        return;
    }

    // ===================== SCAN ROLE (R16 skeleton) =====================
    __half (*sW)[1032]    = (__half(*)[1032])(smem);
    __half (*sA)[32][520] = (__half(*)[32][520])(smem + 132096);
    float (*sOut)[72]     = (float(*)[72])(smem + 198656);
    float* sWout          = (float*)(smem + 207872);

    const int nb = blockIdx.x & 15, bb = blockIdx.x >> 4;
    const int wm = wid & 1, wn = wid >> 1;           // 2m x 4n warp grid
    const int er = tid >> 3, ec = (tid & 7) * 8;     // epilogue: row (32), col-group

    // Load persistent W_hh slice (64 x 1024) once
    for (int i = tid; i < 64 * 128; i += 256) {
        const int r = i >> 7, c8 = (i & 127) * 8;
        cp16_ca(&sW[r][c8], g_whh + (size_t)(nb * 64 + r) * HID + c8);
    }
    CP_COMMIT();
    if (tid < 64) sWout[tid] = W_out[nb * 64 + tid];
    CP_WAIT0();
    __syncthreads();

    // wait for xp[0] to be produced
    if (tid == 0) {
        while (*(volatile unsigned*)&g_xready[0] < XRDY_TGT) { }
        __threadfence();
    }
    __syncthreads();

    unsigned* bar = &g_cnt[bb * 32];

    for (int t = 0; t < TT; t++) {
        const __half* __restrict__ hsrc = g_hf[t & 1];

        auto issue = [&](int buf, int k0) {
#pragma unroll
            for (int j = 0; j < 8; j++) {            // 2048 cp16: 32 rows x 64/row
                const int idx = tid + j * 256;
                const int r = idx >> 6, c8 = (idx & 63) * 8;
                cp16_cg(&sA[buf][r][c8], hsrc + (size_t)(bb * 32 + r) * HID + k0 + c8);
            }
        };
        issue(0, 0); CP_COMMIT();
        issue(1, CHUNK); CP_COMMIT();

        // prefetch xp (fp16) for the epilogue (overlaps h loads + MMAs)
        float xs[8];
        {
            const __half* xpp = g_xp + ((size_t)t * BB + bb * 32 + er) * HID + nb * 64 + ec;
            uint4 xv = __ldcg((const uint4*)xpp);
            const __half2* xh2 = (const __half2*)&xv;
#pragma unroll
            for (int j = 0; j < 4; j++) {
                float2 f2 = __half22float2(xh2[j]);
                xs[2 * j] = f2.x; xs[2 * j + 1] = f2.y;
            }
        }

        wmma::fragment<wmma::accumulator, 16, 16, 16, float> acc;
        wmma::fill_fragment(acc, 0.0f);

        CP_WAIT1();                                   // chunk 0 landed
        __syncthreads();
#pragma unroll
        for (int s = 0; s < CHUNK; s += 16) {
            wmma::fragment<wmma::matrix_a, 16, 16, 16, __half, wmma::row_major> ah;
            wmma::fragment<wmma::matrix_b, 16, 16, 16, __half, wmma::col_major> bh;
            wmma::load_matrix_sync(ah, &sA[0][wm * 16][s], 520);
            wmma::load_matrix_sync(bh, &sW[wn * 16][s], 1032);
            wmma::mma_sync(acc, ah, bh, acc);
        }
        CP_WAIT0();                                   // chunk 1 landed
        __syncthreads();
#pragma unroll
        for (int s = 0; s < CHUNK; s += 16) {
            wmma::fragment<wmma::matrix_a, 16, 16, 16, __half, wmma::row_major> ah;
            wmma::fragment<wmma::matrix_b, 16, 16, 16, __half, wmma::col_major> bh;
            wmma::load_matrix_sync(ah, &sA[1][wm * 16][s], 520);
            wmma::load_matrix_sync(bh, &sW[wn * 16][CHUNK + s], 1032);
            wmma::mma_sync(acc, ah, bh, acc);
        }
        wmma::store_matrix_sync(&sOut[wm * 16][wn * 16], acc, 72, wmma::mem_row_major);
        __syncthreads();

        // ---- epilogue: tanh + fp16 h store + z partial ----
        const int bglob = bb * 32 + er;
        __half hb[8];
        float z = 0.0f;
#pragma unroll
        for (int j = 0; j < 8; j++) {
            float f = fast_tanh(xs[j] + sOut[er][ec + j]);
            z += f * sWout[ec + j];
            hb[j] = __float2half(f);
        }
        *(uint4*)(g_hf[(t & 1) ^ 1] + (size_t)bglob * HID + nb * 64 + ec) = *(uint4*)hb;

        // reduce z across the 8 lanes covering this row
        z += __shfl_xor_sync(0xffffffffu, z, 1);
        z += __shfl_xor_sync(0xffffffffu, z, 2);
        z += __shfl_xor_sync(0xffffffffu, z, 4);
        if ((tid & 7) == 0) g_zp[nb][t * BB + bglob] = z;

        // ---- per-bb-group barrier + xp[t+1] readiness (same spin) ----
        __syncthreads();
        if (tid == 0) {
            __threadfence();                          // release h stores (cumulative)
            atomicAdd(bar, 1u);
            const unsigned tgt = 16u * (unsigned)(t + 1);
            while (*(volatile unsigned*)bar < tgt) { }
            if (t + 1 < TT)
                while (*(volatile unsigned*)&g_xready[t + 1] < XRDY_TGT) { }
            __threadfence();                          // acquire peers' h + xp stores
        }
        __syncthreads();
    }
}

// ---------------------------------------------------------------------------
// reduce z partials: g_zsum[b][t] = sum_nb g_zp[nb][t*BB+b]
// ---------------------------------------------------------------------------
__global__ void reduce_z() {
    int idx = blockIdx.x * blockDim.x + threadIdx.x;
    int b = idx & 255, t = idx >> 8;
    float s = 0.0f;
#pragma unroll
    for (int p = 0; p < 16; p++) s += g_zp[p][idx];
    g_zsum[b * TT + t] = s;
}

// ---------------------------------------------------------------------------
// output scan
// ---------------------------------------------------------------------------
__global__ void out_kernel(const float* __restrict__ b_out,
                           const float* __restrict__ w_r,
                           const float* __restrict__ b_r,
                           float* __restrict__ out) {
    const int b = threadIdx.x;
    const float bo = b_out[0], wr = w_r[0], br = b_r[0];
    float o = 0.0f;
    for (int t4 = 0; t4 < TT; t4 += 4) {
        float4 z4 = *(const float4*)(g_zsum + b * TT + t4);
        float zz[4] = {z4.x, z4.y, z4.z, z4.w};
        float oo[4];
#pragma unroll
        for (int j = 0; j < 4; j++) {
            float arg = (t4 + j == 0) ? (zz[j] + bo) : (zz[j] + bo + wr * o + br);
            o = 1.0f / (1.0f + __expf(-arg));
            oo[j] = o;
        }
        *(float4*)(out + b * TT + t4) = make_float4(oo[0], oo[1], oo[2], oo[3]);
    }
}

// ---------------------------------------------------------------------------
// Launch
// ---------------------------------------------------------------------------
extern "C" void kernel_launch(void* const* d_in, const int* in_sizes, int n_in,
                              void* d_out, int out_size) {
    const float* x     = (const float*)d_in[0];
    const float* W_ih  = (const float*)d_in[1];
    const float* b_ih  = (const float*)d_in[2];
    const float* W_hh  = (const float*)d_in[3];
    const float* b_hh  = (const float*)d_in[4];
    const float* W_out = (const float*)d_in[5];
    const float* b_out = (const float*)d_in[6];
    const float* w_r   = (const float*)d_in[7];
    const float* b_r   = (const float*)d_in[8];
    float* out = (float*)d_out;

    cudaFuncSetAttribute(step_fused, cudaFuncAttributeMaxDynamicSharedMemorySize, 208128);

    init_kernel<<<128, 256>>>();
    prep_whh<<<(HID * HID / 8) / 256, 256>>>(W_hh);
    prep_wih<<<(HID * 32) / 256, 256>>>(W_ih);
    prep_x<<<(TT * BB * 32) / 256, 256>>>(x);
    step_fused<<<NGRID, 256, 208128>>>(W_out, b_ih, b_hh);
    reduce_z<<<(TT * BB) / 256, 256>>>();
    out_kernel<<<1, 256>>>(b_out, w_r, b_r, out);
}